// round 1
// baseline (speedup 1.0000x reference)
#include <cuda_runtime.h>
#include <cuda_bf16.h>

// ---------------------------------------------------------------------------
// IterativeEmbeddingModel: 2 iterations of
//   emb <- concat(emb@T1, seg_sum(emb[col],row)@T2, seg_sum_anti(...)@T3)
// Optimization: aggregation is linear, so compute Y = emb @ [T1|T2|T3] first,
// then aggregate the 64-wide Y2/Y3 slices (3x less gather traffic).
// Aggregation is atomic-free via a CSR built once per launch.
// GEMM uses fma.rn.f32x2 packed fp32 (2x FFMA throughput on Blackwell).
// ---------------------------------------------------------------------------

#define NMAX 50000
#define EMAX 400000
#define DIM  192
#define PP   64

typedef unsigned long long ull;

// Scratch (device globals; no allocation APIs allowed)
__device__ int   g_count[2 * NMAX];
__device__ int   g_cursor[2 * NMAX];
__device__ int   g_rowstart[2 * (NMAX + 1)];
__device__ int   g_blocksum[2 * 128];
__device__ int   g_cols[2 * EMAX];
__device__ float g_emb1[(size_t)NMAX * DIM];   // iteration-1 output
__device__ float g_Y[(size_t)NMAX * 128];      // [Y2 | Y3] per row

// ---- packed f32x2 helpers -------------------------------------------------
__device__ __forceinline__ ull pack_dup(float a) {
    ull r; asm("mov.b64 %0, {%1, %1};" : "=l"(r) : "f"(a)); return r;
}
__device__ __forceinline__ void fma2(ull &c, ull a, ull b) {
    asm("fma.rn.f32x2 %0, %1, %2, %0;" : "+l"(c) : "l"(a), "l"(b));
}
__device__ __forceinline__ float2 unpack2(ull v) {
    float2 f; asm("mov.b64 {%0, %1}, %2;" : "=f"(f.x), "=f"(f.y) : "l"(v)); return f;
}

// ---- CSR build ------------------------------------------------------------
__global__ void zero_counts_kernel() {
    int i = blockIdx.x * blockDim.x + threadIdx.x;
    if (i < 2 * NMAX) g_count[i] = 0;
}

__global__ void hist_kernel(const int* __restrict__ e0, const int* __restrict__ e1, int nE) {
    int i = blockIdx.x * blockDim.x + threadIdx.x;
    if (i >= 2 * nE) return;
    int l = (i < nE) ? 0 : 1;
    const int* p = l ? e1 : e0;
    int e = l ? (i - nE) : i;
    int d = p[e];                 // destination row
    atomicAdd(&g_count[l * NMAX + d], 1);
}

__global__ void scan_partial_kernel(int n) {
    __shared__ int sh[512];
    int l = blockIdx.y;
    int i = blockIdx.x * 512 + threadIdx.x;
    int v = (i < n) ? g_count[l * NMAX + i] : 0;
    sh[threadIdx.x] = v;
    __syncthreads();
    for (int off = 1; off < 512; off <<= 1) {
        int t = (threadIdx.x >= off) ? sh[threadIdx.x - off] : 0;
        __syncthreads();
        sh[threadIdx.x] += t;
        __syncthreads();
    }
    if (i < n) g_rowstart[l * (NMAX + 1) + i] = sh[threadIdx.x] - v;  // exclusive
    if (threadIdx.x == 511) g_blocksum[l * 128 + blockIdx.x] = sh[511];
}

__global__ void scan_tops_kernel(int n, int nb) {
    if (blockIdx.x == 0 && threadIdx.x == 0) {
        for (int l = 0; l < 2; l++) {
            int run = 0;
            for (int b = 0; b < nb; b++) {
                int t = g_blocksum[l * 128 + b];
                g_blocksum[l * 128 + b] = run;
                run += t;
            }
            g_rowstart[l * (NMAX + 1) + n] = run;
        }
    }
}

__global__ void add_offsets_kernel(int n) {
    int l = blockIdx.y;
    int i = blockIdx.x * blockDim.x + threadIdx.x;
    if (i < n) {
        g_rowstart[l * (NMAX + 1) + i] += g_blocksum[l * 128 + (i >> 9)];
        g_cursor[l * NMAX + i] = 0;
    }
}

__global__ void fill_kernel(const int* __restrict__ e0, const int* __restrict__ e1, int nE) {
    int i = blockIdx.x * blockDim.x + threadIdx.x;
    if (i >= 2 * nE) return;
    int l = (i < nE) ? 0 : 1;
    const int* p = l ? e1 : e0;
    int e = l ? (i - nE) : i;
    int d = p[e];
    int c = p[nE + e];
    int pos = g_rowstart[l * (NMAX + 1) + d] + atomicAdd(&g_cursor[l * NMAX + d], 1);
    g_cols[l * EMAX + pos] = c;
}

// ---- GEMM: Y = A @ [T0|T1|T2]; T0 part straight to dst cols[0:64] ---------
// BM=64 rows/block, 256 threads = 16x16 grid, 4x4 micro-tile per theta,
// smem: As[64][193] (+pad, conflict-free) + Bs[192][64]. occ 2.
#define GEMM_SMEM_BYTES ((64 * 193 + DIM * PP) * 4)

__global__ __launch_bounds__(256, 2)
void gemm_kernel(const float* __restrict__ A,
                 const float* __restrict__ T0,
                 const float* __restrict__ T1,
                 const float* __restrict__ T2,
                 float* __restrict__ dst,   // n x 192 (cols 0:64 written here)
                 float* __restrict__ Y,     // n x 128 (Y2|Y3)
                 int n)
{
    extern __shared__ float sm[];
    float* As = sm;                  // [64][193]
    float* Bs = sm + 64 * 193;       // [192][64]
    const int tid = threadIdx.x;
    const int tx = tid & 15, ty = tid >> 4;
    const int rowBase = blockIdx.x * 64;

    // Load A tile (64 x 192), zero-pad OOB rows
    for (int f = tid; f < 64 * 48; f += 256) {
        int r = f / 48, c4 = f % 48;
        int gr = rowBase + r;
        float4 v = make_float4(0.f, 0.f, 0.f, 0.f);
        if (gr < n) v = *(const float4*)(A + (size_t)gr * DIM + c4 * 4);
        float* d = As + r * 193 + c4 * 4;
        d[0] = v.x; d[1] = v.y; d[2] = v.z; d[3] = v.w;
    }

    const float* Tarr[3] = {T0, T1, T2};
#pragma unroll
    for (int t = 0; t < 3; ++t) {
        __syncthreads();
        const float4* Tp = (const float4*)Tarr[t];
        float4* B4 = (float4*)Bs;
        for (int f = tid; f < DIM * PP / 4; f += 256) B4[f] = Tp[f];
        __syncthreads();

        ull acc00 = 0, acc01 = 0, acc10 = 0, acc11 = 0;
        ull acc20 = 0, acc21 = 0, acc30 = 0, acc31 = 0;
        const float* Ap = As + (ty * 4) * 193;
#pragma unroll 4
        for (int k = 0; k < DIM; k++) {
            ull b01 = *(const ull*)(Bs + k * 64 + tx * 4);
            ull b23 = *(const ull*)(Bs + k * 64 + tx * 4 + 2);
            ull a0 = pack_dup(Ap[0 * 193 + k]);
            ull a1 = pack_dup(Ap[1 * 193 + k]);
            ull a2 = pack_dup(Ap[2 * 193 + k]);
            ull a3 = pack_dup(Ap[3 * 193 + k]);
            fma2(acc00, a0, b01); fma2(acc01, a0, b23);
            fma2(acc10, a1, b01); fma2(acc11, a1, b23);
            fma2(acc20, a2, b01); fma2(acc21, a2, b23);
            fma2(acc30, a3, b01); fma2(acc31, a3, b23);
        }

        ull accs[4][2] = {{acc00, acc01}, {acc10, acc11}, {acc20, acc21}, {acc30, acc31}};
#pragma unroll
        for (int i = 0; i < 4; i++) {
            int gr = rowBase + ty * 4 + i;
            if (gr < n) {
                float2 lo = unpack2(accs[i][0]);
                float2 hi = unpack2(accs[i][1]);
                float4 v = make_float4(lo.x, lo.y, hi.x, hi.y);
                if (t == 0) *(float4*)(dst + (size_t)gr * DIM + tx * 4) = v;
                else        *(float4*)(Y + (size_t)gr * 128 + (t - 1) * 64 + tx * 4) = v;
            }
        }
    }
}

// ---- Aggregation: warp per node, atomic-free CSR gather -------------------
// dst[node, 64:128]  = sum_{edges}  Y[col, 0:64]
// dst[node, 128:192] = sum_{anti}   Y[col, 64:128]
__global__ void agg_kernel(const float* __restrict__ Y, float* __restrict__ dst, int n)
{
    int gw = (blockIdx.x * blockDim.x + threadIdx.x) >> 5;
    int lane = threadIdx.x & 31;
    if (gw >= n) return;
#pragma unroll
    for (int l = 0; l < 2; ++l) {
        const int* rs = g_rowstart + l * (NMAX + 1);
        const int* cs = g_cols + l * EMAX;
        int s = __ldg(rs + gw);
        int e = __ldg(rs + gw + 1);
        const float* Yb = Y + l * 64 + lane * 2;
        float ax = 0.f, ay = 0.f;
        int j = s;
        for (; j + 4 <= e; j += 4) {        // unroll-4 for MLP
            int c0 = cs[j], c1 = cs[j + 1], c2 = cs[j + 2], c3 = cs[j + 3];
            float2 v0 = *(const float2*)(Yb + (size_t)c0 * 128);
            float2 v1 = *(const float2*)(Yb + (size_t)c1 * 128);
            float2 v2 = *(const float2*)(Yb + (size_t)c2 * 128);
            float2 v3 = *(const float2*)(Yb + (size_t)c3 * 128);
            ax += (v0.x + v1.x) + (v2.x + v3.x);
            ay += (v0.y + v1.y) + (v2.y + v3.y);
        }
        for (; j < e; ++j) {
            float2 v = *(const float2*)(Yb + (size_t)cs[j] * 128);
            ax += v.x; ay += v.y;
        }
        float2 o = make_float2(ax, ay);
        *(float2*)(dst + (size_t)gw * DIM + 64 + l * 64 + lane * 2) = o;
    }
}

// ---------------------------------------------------------------------------
extern "C" void kernel_launch(void* const* d_in, const int* in_sizes, int n_in,
                              void* d_out, int out_size)
{
    const float* emb = (const float*)d_in[0];
    const float* t1  = (const float*)d_in[1];
    const float* t2  = (const float*)d_in[2];
    const float* t3  = (const float*)d_in[3];
    const int*   e0  = (const int*)d_in[4];
    const int*   e1  = (const int*)d_in[5];
    // d_in[6] = num_iterations (fixed at 2 for this problem)

    int n  = in_sizes[0] / DIM;
    int nE = in_sizes[4] / 2;
    float* out = (float*)d_out;

    void *p_emb1_v, *p_Y_v;
    cudaGetSymbolAddress(&p_emb1_v, g_emb1);
    cudaGetSymbolAddress(&p_Y_v, g_Y);
    float* p_emb1 = (float*)p_emb1_v;
    float* p_Y    = (float*)p_Y_v;

    cudaFuncSetAttribute(gemm_kernel, cudaFuncAttributeMaxDynamicSharedMemorySize,
                         GEMM_SMEM_BYTES);

    // --- CSR build (once; shared by both iterations) ---
    zero_counts_kernel<<<(2 * NMAX + 255) / 256, 256>>>();
    hist_kernel<<<(2 * nE + 255) / 256, 256>>>(e0, e1, nE);
    int nb = (n + 511) / 512;
    dim3 gscan(nb, 2);
    scan_partial_kernel<<<gscan, 512>>>(n);
    scan_tops_kernel<<<1, 1>>>(n, nb);
    dim3 goff((n + 255) / 256, 2);
    add_offsets_kernel<<<goff, 256>>>(n);
    fill_kernel<<<(2 * nE + 255) / 256, 256>>>(e0, e1, nE);

    int gemm_blocks = (n + 63) / 64;
    int agg_blocks = (n * 32 + 255) / 256;

    // --- iteration 1 ---
    gemm_kernel<<<gemm_blocks, 256, GEMM_SMEM_BYTES>>>(emb, t1, t2, t3, p_emb1, p_Y, n);
    agg_kernel<<<agg_blocks, 256>>>(p_Y, p_emb1, n);

    // --- iteration 2 ---
    gemm_kernel<<<gemm_blocks, 256, GEMM_SMEM_BYTES>>>(p_emb1, t1, t2, t3, out, p_Y, n);
    agg_kernel<<<agg_blocks, 256>>>(p_Y, out, n);
}